// round 16
// baseline (speedup 1.0000x reference)
#include <cuda_runtime.h>
#include <cuda_bf16.h>
#include <cstdint>

#define B_ 8
#define C_ 512
#define HW_ 4096
#define PER_IMG (C_*HW_)        // 2,097,152
#define TOT (B_*PER_IMG)        // 16,777,216

// Scratch (allocation-free rule: __device__ globals)
__device__ float g_f[2u*TOT];       // conv outputs / V, both branches
__device__ float g_S[2u*TOT];       // pre-softmax logits, both branches
__device__ float g_Msum[B_*HW_];
__device__ float g_C2[B_*HW_];
// bf16 split operands: W [br*3+s][m*512+k], X transposed [(br*3+s)*8+b][hw*512+c]
__device__ __nv_bfloat16 g_Wsp[6u*C_*C_];
__device__ __nv_bfloat16 g_Xsp[(size_t)6*B_*PER_IMG];

typedef unsigned long long u64;

__device__ __forceinline__ uint32_t smem_u32(const void* p) {
    uint32_t a;
    asm("{ .reg .u64 t; cvta.to.shared.u64 t, %1; cvt.u32.u64 %0, t; }"
        : "=r"(a) : "l"(p));
    return a;
}

// cp.async 16B (compute_80+, legal on compute_103)
#define CP16(sm, g) \
    asm volatile("cp.async.cg.shared.global [%0], [%1], 16;" \
                 :: "r"(sm), "l"(g) : "memory")
#define CP_COMMIT() asm volatile("cp.async.commit_group;" ::: "memory")
#define CP_WAIT1()  asm volatile("cp.async.wait_group 1;" ::: "memory")
#define CP_WAIT0()  asm volatile("cp.async.wait_group 0;" ::: "memory")

#define LDM_X4(r0,r1,r2,r3,addr) \
    asm volatile("ldmatrix.sync.aligned.m8n8.x4.shared.b16 {%0,%1,%2,%3}, [%4];" \
                 : "=r"(r0),"=r"(r1),"=r"(r2),"=r"(r3) : "r"(addr))
#define LDM_X2(r0,r1,addr) \
    asm volatile("ldmatrix.sync.aligned.m8n8.x2.shared.b16 {%0,%1}, [%2];" \
                 : "=r"(r0),"=r"(r1) : "r"(addr))

#define MMA16816(c, a, bfr) \
    asm volatile("mma.sync.aligned.m16n8k16.row.col.f32.bf16.bf16.f32 " \
                 "{%0,%1,%2,%3}, {%4,%5,%6,%7}, {%8,%9}, {%0,%1,%2,%3};" \
                 : "+f"((c)[0]), "+f"((c)[1]), "+f"((c)[2]), "+f"((c)[3]) \
                 : "r"((a)[0]), "r"((a)[1]), "r"((a)[2]), "r"((a)[3]), \
                   "r"((bfr)[0]), "r"((bfr)[1]))

// Packed fp32x2 FMA (syrk)
__device__ __forceinline__ u64 ffma2(u64 a, u64 b, u64 c) {
    u64 d;
    asm("fma.rn.f32x2 %0, %1, %2, %3;" : "=l"(d) : "l"(a), "l"(b), "l"(c));
    return d;
}
__device__ __forceinline__ u64 pack_dup(float x) {
    u64 r; unsigned xi = __float_as_uint(x);
    asm("mov.b64 %0, {%1, %1};" : "=l"(r) : "r"(xi));
    return r;
}

// ---------------------------------------------------------------------------
// Split kernels: fp32 -> 3 bf16 components (b0=bf16(x), b1=bf16(x-b0), ...)
// ---------------------------------------------------------------------------
__global__ __launch_bounds__(256) void split_w(const float* __restrict__ Wo,
                                               const float* __restrict__ Ws)
{
    int idx = blockIdx.x * 256 + threadIdx.x;      // 0 .. 2*262144-1
    int br = idx >> 18, e = idx & 262143;
    float x = (br ? Ws : Wo)[e];
    __nv_bfloat16 b0 = __float2bfloat16(x);
    float r1 = x - __bfloat162float(b0);
    __nv_bfloat16 b1 = __float2bfloat16(r1);
    __nv_bfloat16 b2 = __float2bfloat16(r1 - __bfloat162float(b1));
    size_t base = (size_t)(br * 3) * (C_ * C_);
    g_Wsp[base + e]               = b0;
    g_Wsp[base + C_*C_ + e]       = b1;
    g_Wsp[base + 2u*C_*C_ + e]    = b2;
}

// X: [c][hw] fp32 -> transposed [hw][c] bf16 x3. 32x32 smem-tiled transpose.
__global__ __launch_bounds__(256) void split_x(const float* __restrict__ opt,
                                               const float* __restrict__ sar)
{
    __shared__ float t[32][33];
    const int zz = blockIdx.z, br = zz >> 3, b = zz & 7;
    const float* X = (br ? sar : opt) + (size_t)b * PER_IMG;
    const int hw0 = blockIdx.x << 5, c0 = blockIdx.y << 5;
    const int tx = threadIdx.x, ty = threadIdx.y;

    #pragma unroll
    for (int i = ty; i < 32; i += 8)
        t[i][tx] = X[(size_t)(c0 + i) * HW_ + hw0 + tx];
    __syncthreads();

    __nv_bfloat16* o0 = g_Xsp + ((size_t)(br * 3 + 0) * B_ + b) * PER_IMG;
    __nv_bfloat16* o1 = g_Xsp + ((size_t)(br * 3 + 1) * B_ + b) * PER_IMG;
    __nv_bfloat16* o2 = g_Xsp + ((size_t)(br * 3 + 2) * B_ + b) * PER_IMG;
    #pragma unroll
    for (int i = ty; i < 32; i += 8) {
        float x = t[tx][i];
        __nv_bfloat16 b0 = __float2bfloat16(x);
        float r1 = x - __bfloat162float(b0);
        __nv_bfloat16 b1 = __float2bfloat16(r1);
        __nv_bfloat16 b2 = __float2bfloat16(r1 - __bfloat162float(b1));
        size_t oi = (size_t)(hw0 + i) * C_ + c0 + tx;
        o0[oi] = b0; o1[oi] = b1; o2[oi] = b2;
    }
}

// ---------------------------------------------------------------------------
// conv_mma: C[m,n] = sum_k W[m,k] X[k,n] via mma.sync m16n8k16 bf16 (HMMA),
// 6 split products folded into virtual K = 6*512 = 96 BK=32 iterations.
// Block 128x128, 8 warps of 64x32, cp.async double-buffered smem.
// smem rows padded to 40 bf16 (80B): conflict-free ldmatrix (20i mod 32 cycle).
// Both A ([m][k]) and B ([n][k]) are K-major -> plain non-trans ldmatrix.
// ---------------------------------------------------------------------------
__global__ __launch_bounds__(256, 2) void conv_mma()
{
    __shared__ __align__(16) __nv_bfloat16 As[2][128][40];
    __shared__ __align__(16) __nv_bfloat16 Bs[2][128][40];

    const int tid = threadIdx.x;
    const int zz = blockIdx.z, br = zz >> 3, b = zz & 7;
    const int mBase = blockIdx.y << 7, nBase = blockIdx.x << 7;

    const __nv_bfloat16* Wb = g_Wsp + (size_t)(br * 3) * (C_ * C_);
    const __nv_bfloat16* Xb = g_Xsp + ((size_t)(br * 3) * B_ + b) * PER_IMG;

    const uint32_t aB = smem_u32(&As[0][0][0]);
    const uint32_t bB = smem_u32(&Bs[0][0][0]);

    // Loader mapping: thread -> (row, 16-elem half)
    const int lrow = tid >> 1, lhalf = tid & 1;
    const __nv_bfloat16* gA0 = Wb + (size_t)(mBase + lrow) * C_ + lhalf * 16;
    const __nv_bfloat16* gB0 = Xb + (size_t)(nBase + lrow) * C_ + lhalf * 16;
    const uint32_t sA0 = aB + lrow * 80 + lhalf * 32;
    const uint32_t sB0 = bB + lrow * 80 + lhalf * 32;

    // MMA mapping
    const int lane = tid & 31, w = tid >> 5;
    const int wm = (w >> 2) * 64, wn = (w & 3) * 32;
    const int lrowA = ((lane >> 3) & 1) * 8 + (lane & 7);
    const int lcolA = ((lane >> 4) & 1) * 16;           // bytes
    const int lrowB = lane & 7;
    const int lcolB = ((lane >> 3) & 1) * 16;           // bytes (lanes 0-15)

    float acc[4][4][4];
    #pragma unroll
    for (int i = 0; i < 4; i++)
        #pragma unroll
        for (int j = 0; j < 4; j++)
            #pragma unroll
            for (int k = 0; k < 4; k++) acc[i][j][k] = 0.f;

    // issue loads for virtual-K iteration q into buffer buf
    auto issue = [&](int q, int buf) {
        const int pass = q >> 4, k0 = (q & 15) << 5;
        const int sa = (0x910 >> (2 * pass)) & 3;   // 0,0,1,0,1,2
        const int sb = (0x184 >> (2 * pass)) & 3;   // 0,1,0,2,1,0
        const __nv_bfloat16* ga = gA0 + (size_t)sa * (C_ * C_) + k0;
        const __nv_bfloat16* gb = gB0 + (size_t)sb * ((size_t)B_ * PER_IMG) + k0;
        const uint32_t da = sA0 + buf * 10240;
        const uint32_t db = sB0 + buf * 10240;
        CP16(da,      ga);
        CP16(da + 16, ga + 8);
        CP16(db,      gb);
        CP16(db + 16, gb + 8);
        CP_COMMIT();
    };

    issue(0, 0);

    for (int q = 0; q < 96; q++) {
        const int buf = q & 1;
        if (q < 95) { issue(q + 1, buf ^ 1); CP_WAIT1(); }
        else        { CP_WAIT0(); }
        __syncthreads();

        const uint32_t aT = aB + buf * 10240;
        const uint32_t bT = bB + buf * 10240;
        #pragma unroll
        for (int kk = 0; kk < 2; kk++) {
            uint32_t afr[4][4], bfr[4][2];
            #pragma unroll
            for (int mt = 0; mt < 4; mt++)
                LDM_X4(afr[mt][0], afr[mt][1], afr[mt][2], afr[mt][3],
                       aT + (wm + mt * 16 + lrowA) * 80 + kk * 32 + lcolA);
            #pragma unroll
            for (int nt = 0; nt < 4; nt++)
                LDM_X2(bfr[nt][0], bfr[nt][1],
                       bT + (wn + nt * 8 + lrowB) * 80 + kk * 32 + lcolB);
            #pragma unroll
            for (int mt = 0; mt < 4; mt++)
                #pragma unroll
                for (int nt = 0; nt < 4; nt++)
                    MMA16816(acc[mt][nt], afr[mt], bfr[nt]);
        }
        __syncthreads();
    }

    // Epilogue: direct fp32 stores (8B per reg pair)
    float* F = g_f + (size_t)zz * PER_IMG;
    const int g4 = lane >> 2, q4 = lane & 3;
    #pragma unroll
    for (int mt = 0; mt < 4; mt++) {
        #pragma unroll
        for (int nt = 0; nt < 4; nt++) {
            const int m = mBase + wm + mt * 16 + g4;
            const int n = nBase + wn + nt * 8 + q4 * 2;
            float2 v0 = { acc[mt][nt][0], acc[mt][nt][1] };
            float2 v1 = { acc[mt][nt][2], acc[mt][nt][3] };
            *(float2*)(F + (size_t)m * HW_ + n) = v0;
            *(float2*)(F + (size_t)(m + 8) * HW_ + n) = v1;
        }
    }
}

// ---------------------------------------------------------------------------
// Kernel B: S_bc = A^T A, A = f[b,c] (64x64). One block per (br,b,c).
// ---------------------------------------------------------------------------
__global__ __launch_bounds__(256) void syrk_kernel()
{
    __shared__ float As[64][68];

    const int cc = blockIdx.x, b = blockIdx.y, br = blockIdx.z;
    const size_t base = (size_t)(br * B_ + b) * PER_IMG + (size_t)cc * HW_;
    const float* A = g_f + base;
    const int tid = threadIdx.x;

    for (int idx = tid * 4; idx < 4096; idx += 1024) {
        float4 v = *(const float4*)(A + idx);
        *(float4*)&As[idx >> 6][idx & 63] = v;
    }
    __syncthreads();

    const int tx = tid & 15, ty = tid >> 4;
    const int i0 = ty << 2, j0 = tx << 2;
    u64 acc[4][2] = {};

    #pragma unroll 8
    for (int h = 0; h < 64; h++) {
        float4 a = *(const float4*)&As[h][i0];
        const u64* bp = (const u64*)&As[h][j0];
        u64 b0 = bp[0], b1 = bp[1];
        float ar[4] = { a.x, a.y, a.z, a.w };
        #pragma unroll
        for (int ii = 0; ii < 4; ii++) {
            u64 ad = pack_dup(ar[ii]);
            acc[ii][0] = ffma2(ad, b0, acc[ii][0]);
            acc[ii][1] = ffma2(ad, b1, acc[ii][1]);
        }
    }

    float* S = g_S + base;
    #pragma unroll
    for (int ii = 0; ii < 4; ii++) {
        u64* dst = (u64*)(S + (size_t)(i0 + ii) * 64 + j0);
        dst[0] = acc[ii][0]; dst[1] = acc[ii][1];
    }
}

// ---------------------------------------------------------------------------
// Kernel C: channel-axis softmax stats; combined Msum and (z1*z2)^-2.
// ---------------------------------------------------------------------------
__global__ __launch_bounds__(256) void softmax_stats()
{
    const int i = blockIdx.x, b = blockIdx.y;
    const int tid = threadIdx.x;
    const int j = tid & 63, slice = tid >> 6;

    __shared__ float red_m[4][64], red_z[4][64];
    __shared__ float res_m[2][64], res_z[2][64];

    for (int br = 0; br < 2; br++) {
        const float* S = g_S + (size_t)(br * B_ + b) * PER_IMG + i * 64 + j;
        float m = -1e30f, z = 0.f;
        for (int cc = slice; cc < C_; cc += 4) {
            float v = S[(size_t)cc * HW_];
            if (v > m) { z = z * __expf(m - v) + 1.f; m = v; }
            else       { z += __expf(v - m); }
        }
        red_m[slice][j] = m; red_z[slice][j] = z;
        __syncthreads();
        if (slice == 0) {
            #pragma unroll
            for (int s = 1; s < 4; s++) {
                float m2 = red_m[s][j], z2 = red_z[s][j];
                float M = fmaxf(m, m2);
                z = z * __expf(m - M) + z2 * __expf(m2 - M);
                m = M;
            }
            res_m[br][j] = m; res_z[br][j] = z;
        }
        __syncthreads();
    }

    if (tid < 64) {
        float msum = res_m[0][j] + res_m[1][j];
        float rz = 1.f / (res_z[0][j] * res_z[1][j]);
        g_Msum[b * HW_ + i * 64 + j] = msum;
        g_C2[b * HW_ + i * 64 + j] = rz * rz;
    }
}

// ---------------------------------------------------------------------------
// Kernel D: Att = f1*f2*exp(2*(s1+s2-Msum))*(z1*z2)^-2. At DRAM roofline.
// ---------------------------------------------------------------------------
__global__ __launch_bounds__(256) void final_kernel(float* __restrict__ out)
{
    const int g = blockIdx.x * 256 + threadIdx.x;
    const size_t e = (size_t)g << 2;
    const int b = (int)(e / PER_IMG);
    const int s = (int)(e & (HW_ - 1));

    const float4 f1 = *(const float4*)(g_f + e);
    const float4 f2 = *(const float4*)(g_f + (size_t)TOT + e);
    const float4 s1 = *(const float4*)(g_S + e);
    const float4 s2 = *(const float4*)(g_S + (size_t)TOT + e);
    const float4 ms = *(const float4*)(g_Msum + b * HW_ + s);
    const float4 c2 = *(const float4*)(g_C2 + b * HW_ + s);

    float4 o;
    o.x = f1.x * f2.x * __expf(2.f * (s1.x + s2.x - ms.x)) * c2.x;
    o.y = f1.y * f2.y * __expf(2.f * (s1.y + s2.y - ms.y)) * c2.y;
    o.z = f1.z * f2.z * __expf(2.f * (s1.z + s2.z - ms.z)) * c2.z;
    o.w = f1.w * f2.w * __expf(2.f * (s1.w + s2.w - ms.w)) * c2.w;
    *(float4*)(out + e) = o;
}

// ---------------------------------------------------------------------------
extern "C" void kernel_launch(void* const* d_in, const int* in_sizes, int n_in,
                              void* d_out, int out_size)
{
    const float* big[2]   = { nullptr, nullptr };
    const float* small[2] = { nullptr, nullptr };
    int nb = 0, ns = 0;
    for (int i = 0; i < n_in; i++) {
        if (in_sizes[i] >= TOT) { if (nb < 2) big[nb] = (const float*)d_in[i]; nb++; }
        else                    { if (ns < 2) small[ns] = (const float*)d_in[i]; ns++; }
    }

    split_w       <<<2048, 256>>>(small[0], small[1]);
    split_x       <<<dim3(128, 16, 16), dim3(32, 8)>>>(big[0], big[1]);
    conv_mma      <<<dim3(32, 4, 16), 256>>>();
    syrk_kernel   <<<dim3(512, 8, 2), 256>>>();
    softmax_stats <<<dim3(64, 8),     256>>>();
    final_kernel  <<<TOT / 4 / 256,   256>>>((float*)d_out);
}